// round 10
// baseline (speedup 1.0000x reference)
#include <cuda_runtime.h>
#include <cstdint>

// out = relu(x @ (gamma*W3 + W4)^T)
// (reference softmax is over a size-1 axis == 1.0 -> attention is identity on
//  the W3 branch; W1/W2 are dead inputs)
//
// R7 sat at exactly the FFMA2-pipe floor ratio (fma busy 47.5% == floor/period):
// per-SMSP warp count (6.25) was too low to cover LDS/store/overhead latency,
// and the 40-reg weight footprint per 2-col thread capped threads/SM at 800.
//
// NEW: split the 200 output columns across TWO co-resident blocks (col-half
// per block) -> 20 weight regs/thread -> __launch_bounds__(800, 2) -> 1600
// threads = 50 warps/SM. Grid = 296 = 148 tile-streams x 2 col-halves; each
// block runs its own 4-deep cp.async ring over 128-row x tiles (x is read by
// both halves; it's only 21 MB, L2-shared).
// Thread (cp, rl): cols {colbase+2cp, colbase+2cp+1}, rows rl, rl+16, ... of
// the tile. Weights (2 rows of gamma*W3+W4) in registers as packed f32x2;
// FFMA2 (fma.rn.f32x2) doubles the fp32 FMA rate.

#define DICT 20
#define OUTC 200
#define NSTREAMS 148
#define NBLK (2 * NSTREAMS)
#define TPB 800
#define TILE 128
#define NSLOT 4
#define CPT 50                       // column-pair threads per row (per half)
#define RLANES 16
#define RPT (TILE / RLANES)          // 8 rows/thread/tile
#define XS_FLOATS (TILE * DICT)      // 2560 floats (10 KB per slot)
#define CPN (XS_FLOATS / 4)          // 640 16-byte copies per tile

// ---- packed f32x2 helpers (sm_103a FFMA2 path, PTX-only) ----
__device__ __forceinline__ unsigned long long pack2(float lo, float hi) {
    unsigned long long r;
    asm("mov.b64 %0, {%1, %2};" : "=l"(r) : "f"(lo), "f"(hi));
    return r;
}
__device__ __forceinline__ unsigned long long fma2(unsigned long long a,
                                                   unsigned long long b,
                                                   unsigned long long c) {
    unsigned long long d;
    asm("fma.rn.f32x2 %0, %1, %2, %3;" : "=l"(d) : "l"(a), "l"(b), "l"(c));
    return d;
}
__device__ __forceinline__ unsigned long long mul2(unsigned long long a,
                                                   unsigned long long b) {
    unsigned long long d;
    asm("mul.rn.f32x2 %0, %1, %2;" : "=l"(d) : "l"(a), "l"(b));
    return d;
}
__device__ __forceinline__ float hadd_relu(unsigned long long v) {
    float2 f;
    asm("mov.b64 {%0, %1}, %2;" : "=f"(f.x), "=f"(f.y) : "l"(v));
    return fmaxf(f.x + f.y, 0.0f);
}
__device__ __forceinline__ uint32_t smem_u32(const void* p) {
    uint32_t a;
    asm("{ .reg .u64 t; cvta.to.shared.u64 t, %1; cvt.u32.u64 %0, t; }"
        : "=r"(a) : "l"(p));
    return a;
}
__device__ __forceinline__ void cp_async16(uint32_t dst, const void* src) {
    asm volatile("cp.async.cg.shared.global [%0], [%1], 16;"
                 :: "r"(dst), "l"(src) : "memory");
}

__global__ __launch_bounds__(TPB, 2)
void fused_gemm_relu(const float* __restrict__ x,
                     const float* __restrict__ W3,
                     const float* __restrict__ W4,
                     const float* __restrict__ gamma,
                     float* __restrict__ out, int ntiles) {
    __shared__ __align__(16) float xs[NSLOT][XS_FLOATS];   // 40 KB / block

    const int tid = threadIdx.x;
    const int colbase = (blockIdx.x & 1) * (OUTC / 2);   // 0 or 100
    const int stream  = blockIdx.x >> 1;                 // 0..147
    const int cp = tid % CPT;                 // cols colbase + {2cp, 2cp+1}
    const int rl = tid / CPT;                 // row lane 0..15

    // Build this thread's 2 combined weight rows in registers (packed f32x2).
    unsigned long long w0[10], w1[10];
    {
        const float g = gamma[0];
        const int c0 = colbase + 2 * cp;
        const float4* a3 = reinterpret_cast<const float4*>(W3 + c0 * DICT);
        const float4* a4 = reinterpret_cast<const float4*>(W4 + c0 * DICT);
        const float4* b3 = reinterpret_cast<const float4*>(W3 + (c0 + 1) * DICT);
        const float4* b4 = reinterpret_cast<const float4*>(W4 + (c0 + 1) * DICT);
        #pragma unroll
        for (int i = 0; i < 5; i++) {
            float4 p3 = a3[i], p4 = a4[i];
            w0[2 * i]     = pack2(fmaf(g, p3.x, p4.x), fmaf(g, p3.y, p4.y));
            w0[2 * i + 1] = pack2(fmaf(g, p3.z, p4.z), fmaf(g, p3.w, p4.w));
            float4 q3 = b3[i], q4 = b4[i];
            w1[2 * i]     = pack2(fmaf(g, q3.x, q4.x), fmaf(g, q3.y, q4.y));
            w1[2 * i + 1] = pack2(fmaf(g, q3.z, q4.z), fmaf(g, q3.w, q4.w));
        }
    }

    // Prologue: issue staging for the first NSLOT tiles (one group per tile).
    #pragma unroll
    for (int k = 0; k < NSLOT; k++) {
        const int tn = stream + k * NSTREAMS;
        if (tn < ntiles && tid < CPN) {
            const float4* src =
                reinterpret_cast<const float4*>(x + (size_t)tn * XS_FLOATS);
            cp_async16(smem_u32(&xs[k][tid * 4]), src + tid);
        }
        asm volatile("cp.async.commit_group;" ::: "memory");
    }

    int slot = 0;
    for (int t = stream; t < ntiles; t += NSTREAMS) {
        // Tile t's staging group is the oldest pending; allow 3 newer pending.
        asm volatile("cp.async.wait_group 3;" ::: "memory");
        __syncthreads();                       // all threads' copies visible

        {
            const float* xb = xs[slot];
            float2* o = reinterpret_cast<float2*>(
                            out + (size_t)(t * TILE + rl) * OUTC + colbase) + cp;
            #pragma unroll
            for (int i = 0; i < RPT; i++) {
                const ulonglong2* xp = reinterpret_cast<const ulonglong2*>(
                    xb + (rl + i * RLANES) * DICT);
                // Interleave LDS with fma groups: keeps the live x set small
                // (~4 regs) so the 40-reg budget holds without spills.
                ulonglong2 v;
                unsigned long long a0, a1;
                v = xp[0];
                a0 = mul2(v.x, w0[0]);      a1 = mul2(v.x, w1[0]);
                a0 = fma2(v.y, w0[1], a0);  a1 = fma2(v.y, w1[1], a1);
                v = xp[1];
                a0 = fma2(v.x, w0[2], a0);  a1 = fma2(v.x, w1[2], a1);
                a0 = fma2(v.y, w0[3], a0);  a1 = fma2(v.y, w1[3], a1);
                v = xp[2];
                a0 = fma2(v.x, w0[4], a0);  a1 = fma2(v.x, w1[4], a1);
                a0 = fma2(v.y, w0[5], a0);  a1 = fma2(v.y, w1[5], a1);
                v = xp[3];
                a0 = fma2(v.x, w0[6], a0);  a1 = fma2(v.x, w1[6], a1);
                a0 = fma2(v.y, w0[7], a0);  a1 = fma2(v.y, w1[7], a1);
                v = xp[4];
                a0 = fma2(v.x, w0[8], a0);  a1 = fma2(v.x, w1[8], a1);
                a0 = fma2(v.y, w0[9], a0);  a1 = fma2(v.y, w1[9], a1);

                *o = make_float2(hadd_relu(a0), hadd_relu(a1));  // STG.64
                o += RLANES * (OUTC / 2);    // 16 rows ahead
            }
        }
        __syncthreads();                       // slot fully consumed

        // Refill this slot with tile t + NSLOT*NSTREAMS (may be empty group).
        const int tn = t + NSLOT * NSTREAMS;
        if (tn < ntiles && tid < CPN) {
            const float4* src =
                reinterpret_cast<const float4*>(x + (size_t)tn * XS_FLOATS);
            cp_async16(smem_u32(&xs[slot][tid * 4]), src + tid);
        }
        asm volatile("cp.async.commit_group;" ::: "memory");

        slot = (slot + 1) & (NSLOT - 1);
    }
}

extern "C" void kernel_launch(void* const* d_in, const int* in_sizes, int n_in,
                              void* d_out, int out_size) {
    const float* x     = (const float*)d_in[0];
    // d_in[1] = W1, d_in[2] = W2 : dead (softmax over size-1 axis == 1)
    const float* W3    = (const float*)d_in[3];
    const float* W4    = (const float*)d_in[4];
    const float* gamma = (const float*)d_in[5];
    float* out = (float*)d_out;

    const int B = in_sizes[0] / DICT;   // 262144
    const int ntiles = B / TILE;        // 2048 (exact)

    fused_gemm_relu<<<NBLK, TPB>>>(x, W3, W4, gamma, out, ntiles);
}

// round 11
// speedup vs baseline: 5.1730x; 5.1730x over previous
#include <cuda_runtime.h>
#include <cstdint>

// out = relu(x @ (gamma*W3 + W4)^T)
// (reference softmax is over a size-1 axis == 1.0 -> attention is identity on
//  the W3 branch; W1/W2 are dead inputs)
//
// R6/R7 both plateaued at ~8450 cyc/tile with issue ~40%: the block-wide
// __syncthreads re-phase-locks every warp each tile (convoy: all warps LDS /
// fma / STG in the same bursts). 200 output cols pack warp-exactly only at
// 25-warp granularity, so the fix is TWO independent 13-warp blocks per SM:
// separate barriers -> phases drift apart -> pipe bursts interleave.
// R9's mistake (launch_bounds(800,2) -> 32-reg cap -> weight spill) is
// avoided: 2 x 416 threads = 832/SM -> 78-reg cap; this body needs 72.
//
// Block = 416 threads: 400 compute (100 col-pairs x 4 row lanes), threads
// 0..319 also run a 4-deep cp.async ring of 64-row x tiles. Grid 296 =
// 2 blocks/SM, single wave, each block its own tile stream (t += 296).
// Thread (cp, rl): cols {2cp,2cp+1}, rows rl, rl+4, ... of the tile.
// Weights (2 rows of gamma*W3+W4) in registers as packed f32x2; FFMA2
// (fma.rn.f32x2) doubles the fp32 FMA rate.

#define DICT 20
#define OUTC 200
#define NBLK 296
#define TPB 416
#define TILE 64
#define NSLOT 4
#define CPT 100                      // column-pair threads per row
#define RLANES 4
#define RPT (TILE / RLANES)          // 16 rows/thread/tile
#define NCOMPUTE (CPT * RLANES)      // 400
#define XS_FLOATS (TILE * DICT)      // 1280 floats (5 KB per slot)
#define CPN (XS_FLOATS / 4)          // 320 16-byte copies per tile

// ---- packed f32x2 helpers (sm_103a FFMA2 path, PTX-only) ----
__device__ __forceinline__ unsigned long long pack2(float lo, float hi) {
    unsigned long long r;
    asm("mov.b64 %0, {%1, %2};" : "=l"(r) : "f"(lo), "f"(hi));
    return r;
}
__device__ __forceinline__ unsigned long long fma2(unsigned long long a,
                                                   unsigned long long b,
                                                   unsigned long long c) {
    unsigned long long d;
    asm("fma.rn.f32x2 %0, %1, %2, %3;" : "=l"(d) : "l"(a), "l"(b), "l"(c));
    return d;
}
__device__ __forceinline__ unsigned long long mul2(unsigned long long a,
                                                   unsigned long long b) {
    unsigned long long d;
    asm("mul.rn.f32x2 %0, %1, %2;" : "=l"(d) : "l"(a), "l"(b));
    return d;
}
__device__ __forceinline__ float hadd_relu(unsigned long long v) {
    float2 f;
    asm("mov.b64 {%0, %1}, %2;" : "=f"(f.x), "=f"(f.y) : "l"(v));
    return fmaxf(f.x + f.y, 0.0f);
}
__device__ __forceinline__ uint32_t smem_u32(const void* p) {
    uint32_t a;
    asm("{ .reg .u64 t; cvta.to.shared.u64 t, %1; cvt.u32.u64 %0, t; }"
        : "=r"(a) : "l"(p));
    return a;
}
__device__ __forceinline__ void cp_async16(uint32_t dst, const void* src) {
    asm volatile("cp.async.cg.shared.global [%0], [%1], 16;"
                 :: "r"(dst), "l"(src) : "memory");
}

__global__ __launch_bounds__(TPB, 2)
void fused_gemm_relu(const float* __restrict__ x,
                     const float* __restrict__ W3,
                     const float* __restrict__ W4,
                     const float* __restrict__ gamma,
                     float* __restrict__ out, int ntiles) {
    __shared__ __align__(16) float xs[NSLOT][XS_FLOATS];   // 20 KB / block

    const int tid = threadIdx.x;
    const int cp = tid % CPT;                 // cols {2cp, 2cp+1}
    const int rl = tid / CPT;                 // row lane 0..3 (compute if <400)
    const bool is_compute = (tid < NCOMPUTE);
    const bool is_stager  = (tid < CPN);

    // Build this thread's 2 combined weight rows in registers (packed f32x2).
    unsigned long long w0[10], w1[10];
    {
        const float g = gamma[0];
        const float4* a3 = reinterpret_cast<const float4*>(W3 + (2 * cp) * DICT);
        const float4* a4 = reinterpret_cast<const float4*>(W4 + (2 * cp) * DICT);
        const float4* b3 = reinterpret_cast<const float4*>(W3 + (2 * cp + 1) * DICT);
        const float4* b4 = reinterpret_cast<const float4*>(W4 + (2 * cp + 1) * DICT);
        #pragma unroll
        for (int i = 0; i < 5; i++) {
            float4 p3 = a3[i], p4 = a4[i];
            w0[2 * i]     = pack2(fmaf(g, p3.x, p4.x), fmaf(g, p3.y, p4.y));
            w0[2 * i + 1] = pack2(fmaf(g, p3.z, p4.z), fmaf(g, p3.w, p4.w));
            float4 q3 = b3[i], q4 = b4[i];
            w1[2 * i]     = pack2(fmaf(g, q3.x, q4.x), fmaf(g, q3.y, q4.y));
            w1[2 * i + 1] = pack2(fmaf(g, q3.z, q4.z), fmaf(g, q3.w, q4.w));
        }
    }

    // Prologue: issue staging for the first NSLOT tiles (one group per tile).
    #pragma unroll
    for (int k = 0; k < NSLOT; k++) {
        const int tn = blockIdx.x + k * NBLK;
        if (tn < ntiles && is_stager) {
            const float4* src =
                reinterpret_cast<const float4*>(x + (size_t)tn * XS_FLOATS);
            cp_async16(smem_u32(&xs[k][tid * 4]), src + tid);
        }
        asm volatile("cp.async.commit_group;" ::: "memory");
    }

    int slot = 0;
    for (int t = blockIdx.x; t < ntiles; t += NBLK) {
        // Tile t's staging group is the oldest pending; allow 3 newer pending.
        asm volatile("cp.async.wait_group 3;" ::: "memory");
        __syncthreads();                       // all threads' copies visible

        if (is_compute) {
            const float* xb = xs[slot];
            float2* o = reinterpret_cast<float2*>(
                            out + (size_t)(t * TILE + rl) * OUTC) + cp;
            #pragma unroll
            for (int i = 0; i < RPT; i++) {
                const ulonglong2* xp = reinterpret_cast<const ulonglong2*>(
                    xb + (rl + i * RLANES) * DICT);
                ulonglong2 v0 = xp[0], v1 = xp[1], v2 = xp[2],
                           v3 = xp[3], v4 = xp[4];

                unsigned long long a0, a1;
                a0 = mul2(v0.x, w0[0]);      a1 = mul2(v0.x, w1[0]);
                a0 = fma2(v0.y, w0[1], a0);  a1 = fma2(v0.y, w1[1], a1);
                a0 = fma2(v1.x, w0[2], a0);  a1 = fma2(v1.x, w1[2], a1);
                a0 = fma2(v1.y, w0[3], a0);  a1 = fma2(v1.y, w1[3], a1);
                a0 = fma2(v2.x, w0[4], a0);  a1 = fma2(v2.x, w1[4], a1);
                a0 = fma2(v2.y, w0[5], a0);  a1 = fma2(v2.y, w1[5], a1);
                a0 = fma2(v3.x, w0[6], a0);  a1 = fma2(v3.x, w1[6], a1);
                a0 = fma2(v3.y, w0[7], a0);  a1 = fma2(v3.y, w1[7], a1);
                a0 = fma2(v4.x, w0[8], a0);  a1 = fma2(v4.x, w1[8], a1);
                a0 = fma2(v4.y, w0[9], a0);  a1 = fma2(v4.y, w1[9], a1);

                *o = make_float2(hadd_relu(a0), hadd_relu(a1));  // STG.64
                o += RLANES * (OUTC / 2);    // 4 rows ahead
            }
        }
        __syncthreads();                       // slot fully consumed

        // Refill this slot with tile t + NSLOT*NBLK (may be empty group).
        const int tn = t + NSLOT * NBLK;
        if (tn < ntiles && is_stager) {
            const float4* src =
                reinterpret_cast<const float4*>(x + (size_t)tn * XS_FLOATS);
            cp_async16(smem_u32(&xs[slot][tid * 4]), src + tid);
        }
        asm volatile("cp.async.commit_group;" ::: "memory");

        slot = (slot + 1) & (NSLOT - 1);
    }
}

extern "C" void kernel_launch(void* const* d_in, const int* in_sizes, int n_in,
                              void* d_out, int out_size) {
    const float* x     = (const float*)d_in[0];
    // d_in[1] = W1, d_in[2] = W2 : dead (softmax over size-1 axis == 1)
    const float* W3    = (const float*)d_in[3];
    const float* W4    = (const float*)d_in[4];
    const float* gamma = (const float*)d_in[5];
    float* out = (float*)d_out;

    const int B = in_sizes[0] / DICT;   // 262144
    const int ntiles = B / TILE;        // 4096 (exact)

    fused_gemm_relu<<<NBLK, TPB>>>(x, W3, W4, gamma, out, ntiles);
}

// round 13
// speedup vs baseline: 5.7645x; 1.1143x over previous
#include <cuda_runtime.h>
#include <cstdint>

// out = relu(x @ (gamma*W3 + W4)^T)
// (reference softmax is over a size-1 axis == 1.0 -> attention is identity on
//  the W3 branch; W1/W2 are dead inputs)
//
// TENSOR PATH via mma.sync (plain-sm_103-legal; tcgen05 needs the sm_103a
// target this harness does not emit). m16n8k8 tf32 HMMA: 1024 MAC/warp-instr
// vs 64 for FFMA2 -> per-64-row-tile instruction count drops ~11K -> ~2.4K,
// removing the issue/fma wall that pinned all FFMA variants at 61-68us.
// fp32 accuracy: 3-term tf32 split  D = xh*wh + xh*wl + xl*wh  (err ~2^-22).
//
// Layout: D[64 x 208pad] = X[64 x 24pad] @ Wc^T. 8 warps/block:
//   warp = (m_blk = wid&3 -> rows 16*m_blk.., half = wid>>2 -> 13 n8-blocks).
// Weights pre-split+pre-packed in smem in B-fragment order
//   [nb][kb][lane]{bh0,bh1,bl0,bl1} -> one LDS.128 per (nb,kb), conflict-free.
// x tiles staged by R7's proven 4-deep cp.async ring. 296 blocks (2/SM).

#define DICT 20
#define OUTC 200
#define NBN 26                        // n8 blocks (208 cols, last 8 padded)
#define NBLK 296
#define TPB 256
#define TILE 64
#define NSLOT 4
#define XS_FLOATS (TILE * DICT)       // 1280 floats = 5120 B / slot
#define CPN (XS_FLOATS / 4)           // 320 16-B copies per tile
#define FRAG_BYTES (NBN * 3 * 32 * 16)   // 39936 B packed B fragments
#define XS_OFF FRAG_BYTES
#define SMEM_BYTES (FRAG_BYTES + NSLOT * XS_FLOATS * 4)   // 60416 B

__device__ __forceinline__ uint32_t smem_u32(const void* p) {
    uint32_t a;
    asm("{ .reg .u64 t; cvta.to.shared.u64 t, %1; cvt.u32.u64 %0, t; }"
        : "=r"(a) : "l"(p));
    return a;
}
__device__ __forceinline__ void cp_async16(uint32_t dst, const void* src) {
    asm volatile("cp.async.cg.shared.global [%0], [%1], 16;"
                 :: "r"(dst), "l"(src) : "memory");
}
__device__ __forceinline__ uint32_t cvt_tf32(float v) {
    uint32_t r;
    asm("cvt.rna.tf32.f32 %0, %1;" : "=r"(r) : "f"(v));
    return r;
}
// D += A(tf32 m16k8) * B(tf32 k8n8), fp32 accumulate, in-place C==D.
__device__ __forceinline__ void mma_tf32(float* c, const uint32_t* a,
                                         uint32_t b0, uint32_t b1) {
    asm volatile(
        "mma.sync.aligned.m16n8k8.row.col.f32.tf32.tf32.f32 "
        "{%0,%1,%2,%3}, {%4,%5,%6,%7}, {%8,%9}, {%0,%1,%2,%3};"
        : "+f"(c[0]), "+f"(c[1]), "+f"(c[2]), "+f"(c[3])
        : "r"(a[0]), "r"(a[1]), "r"(a[2]), "r"(a[3]), "r"(b0), "r"(b1));
}

__global__ __launch_bounds__(TPB, 2)
void fused_gemm_relu_mma(const float* __restrict__ x,
                         const float* __restrict__ W3,
                         const float* __restrict__ W4,
                         const float* __restrict__ gamma,
                         float* __restrict__ out, int ntiles) {
    extern __shared__ __align__(16) char smem[];
    float* xring = reinterpret_cast<float*>(smem + XS_OFF);

    const int tid = threadIdx.x;
    const int wid = tid >> 5;
    const int lane = tid & 31;
    const int m_blk = wid & 3;          // rows [16*m_blk, 16*m_blk+16)
    const int half = wid >> 2;          // n-blocks [13*half, 13*half+13)
    const int r = lane >> 2;            // fragment groupID (row 0..7)
    const int c = lane & 3;             // fragment threadID-in-group

    // ---- Build packed, tf32-split B fragments (once per block) ----
    // Entry (nb, kb, lane): n = nb*8 + lane/4, k0 = kb*8 + lane%4, k1 = k0+4.
    {
        const float g = gamma[0];
        for (int idx = tid; idx < NBN * 3 * 32; idx += TPB) {
            const int nb = idx / 96;
            const int rem = idx % 96;
            const int kb = rem / 32;
            const int ln = rem % 32;
            const int n = nb * 8 + (ln >> 2);
            const int k0 = kb * 8 + (ln & 3);
            const int k1 = k0 + 4;
            float w0 = (n < OUTC && k0 < DICT)
                ? fmaf(g, W3[n * DICT + k0], W4[n * DICT + k0]) : 0.0f;
            float w1 = (n < OUTC && k1 < DICT)
                ? fmaf(g, W3[n * DICT + k1], W4[n * DICT + k1]) : 0.0f;
            uint32_t h0 = cvt_tf32(w0), h1 = cvt_tf32(w1);
            uint32_t l0 = cvt_tf32(w0 - __uint_as_float(h0));
            uint32_t l1 = cvt_tf32(w1 - __uint_as_float(h1));
            float4 v;
            v.x = __uint_as_float(h0); v.y = __uint_as_float(h1);
            v.z = __uint_as_float(l0); v.w = __uint_as_float(l1);
            *reinterpret_cast<float4*>(smem + idx * 16) = v;
        }
    }
    __syncthreads();

    // ---- Prologue: stage first NSLOT x tiles (one cp.async group each) ----
    #pragma unroll
    for (int k = 0; k < NSLOT; k++) {
        const int tn = blockIdx.x + k * NBLK;
        if (tn < ntiles) {
            const float4* src =
                reinterpret_cast<const float4*>(x + (size_t)tn * XS_FLOATS);
            #pragma unroll
            for (int i = 0; i < 2; i++) {
                int idx = tid + i * TPB;
                if (idx < CPN)
                    cp_async16(smem_u32(&xring[k * XS_FLOATS + idx * 4]),
                               src + idx);
            }
        }
        asm volatile("cp.async.commit_group;" ::: "memory");
    }

    int slot = 0;
    for (int t = blockIdx.x; t < ntiles; t += NBLK) {
        asm volatile("cp.async.wait_group 3;" ::: "memory");
        __syncthreads();                 // xring[slot] ready for all threads

        // ---- Load + tf32-split A fragments (3 k-blocks) ----
        const float* xb = xring + slot * XS_FLOATS;
        uint32_t ah[3][4], al[3][4];
        {
            const int row0 = m_blk * 16 + r;
            #pragma unroll
            for (int kb = 0; kb < 3; kb++) {
                float f0 = xb[row0 * DICT + kb * 8 + c];
                float f1 = xb[(row0 + 8) * DICT + kb * 8 + c];
                float f2 = (kb < 2) ? xb[row0 * DICT + kb * 8 + c + 4] : 0.0f;
                float f3 = (kb < 2) ? xb[(row0 + 8) * DICT + kb * 8 + c + 4] : 0.0f;
                ah[kb][0] = cvt_tf32(f0);
                ah[kb][1] = cvt_tf32(f1);
                ah[kb][2] = cvt_tf32(f2);
                ah[kb][3] = cvt_tf32(f3);
                al[kb][0] = cvt_tf32(f0 - __uint_as_float(ah[kb][0]));
                al[kb][1] = cvt_tf32(f1 - __uint_as_float(ah[kb][1]));
                al[kb][2] = cvt_tf32(f2 - __uint_as_float(ah[kb][2]));
                al[kb][3] = cvt_tf32(f3 - __uint_as_float(ah[kb][3]));
            }
        }

        // ---- 13 n-blocks x 3 k-blocks x 3 split terms of HMMA ----
        float acc[13][4];
        #pragma unroll
        for (int nb = 0; nb < 13; nb++)
            #pragma unroll
            for (int j = 0; j < 4; j++) acc[nb][j] = 0.0f;

        const char* fb = smem + ((size_t)(half * 13) * 3 * 32 + lane) * 16;
        #pragma unroll
        for (int nb = 0; nb < 13; nb++) {
            #pragma unroll
            for (int kb = 0; kb < 3; kb++) {
                float4 f = *reinterpret_cast<const float4*>(
                    fb + (size_t)(nb * 3 + kb) * 32 * 16);    // LDS.128
                uint32_t bh0 = __float_as_uint(f.x);
                uint32_t bh1 = __float_as_uint(f.y);
                uint32_t bl0 = __float_as_uint(f.z);
                uint32_t bl1 = __float_as_uint(f.w);
                mma_tf32(acc[nb], ah[kb], bh0, bh1);
                mma_tf32(acc[nb], ah[kb], bl0, bl1);
                mma_tf32(acc[nb], al[kb], bh0, bh1);
            }
        }

        // ---- Epilogue: relu + STG.64 (fragment rows r, r+8) ----
        {
            float* o0 = out + (size_t)(t * TILE + m_blk * 16 + r) * OUTC;
            float* o1 = o0 + 8 * OUTC;
            #pragma unroll
            for (int nb = 0; nb < 13; nb++) {
                const int cb = half * 104 + nb * 8 + c * 2;
                if (cb < OUTC) {
                    *reinterpret_cast<float2*>(o0 + cb) =
                        make_float2(fmaxf(acc[nb][0], 0.0f),
                                    fmaxf(acc[nb][1], 0.0f));
                    *reinterpret_cast<float2*>(o1 + cb) =
                        make_float2(fmaxf(acc[nb][2], 0.0f),
                                    fmaxf(acc[nb][3], 0.0f));
                }
            }
        }
        __syncthreads();                 // slot fully consumed

        // ---- Refill slot with tile t + NSLOT*NBLK (group even if empty) ----
        const int tn = t + NSLOT * NBLK;
        if (tn < ntiles) {
            const float4* src =
                reinterpret_cast<const float4*>(x + (size_t)tn * XS_FLOATS);
            #pragma unroll
            for (int i = 0; i < 2; i++) {
                int idx = tid + i * TPB;
                if (idx < CPN)
                    cp_async16(smem_u32(&xring[slot * XS_FLOATS + idx * 4]),
                               src + idx);
            }
        }
        asm volatile("cp.async.commit_group;" ::: "memory");

        slot = (slot + 1) & (NSLOT - 1);
    }
}

extern "C" void kernel_launch(void* const* d_in, const int* in_sizes, int n_in,
                              void* d_out, int out_size) {
    const float* x     = (const float*)d_in[0];
    // d_in[1] = W1, d_in[2] = W2 : dead (softmax over size-1 axis == 1)
    const float* W3    = (const float*)d_in[3];
    const float* W4    = (const float*)d_in[4];
    const float* gamma = (const float*)d_in[5];
    float* out = (float*)d_out;

    const int B = in_sizes[0] / DICT;   // 262144
    const int ntiles = B / TILE;        // 4096 (exact)

    static int attr_set = 0;
    if (!attr_set) {
        cudaFuncSetAttribute(fused_gemm_relu_mma,
                             cudaFuncAttributeMaxDynamicSharedMemorySize,
                             SMEM_BYTES);
        attr_set = 1;
    }
    fused_gemm_relu_mma<<<NBLK, TPB, SMEM_BYTES>>>(x, W3, W4, gamma, out,
                                                   ntiles);
}